// round 11
// baseline (speedup 1.0000x reference)
#include <cuda_runtime.h>
#include <math.h>

// Fixed problem shape
#define NROWS 32
#define NCH   2
#define LEN   131072
#define KIIR  16384            // FIR truncation; == 2*CHUNK
#define CHUNK 8192
#define THREADS 256
#define SEG   32               // CHUNK == THREADS*SEG
#define NW    (THREADS / 32)   // 8 warps
#define CPR   16               // chunks per row
#define NBLK  (NROWS * CPR)    // 512
#define WIN_J (KIIR / (4 * THREADS)) // 16 float4 Horner steps per thread

// Padded smem index: 4 floats of pad per 32 floats. Keeps 16B alignment for
// float4 smem ops everywhere and makes both access patterns conflict-free:
//  - per-thread segment (base 36*tid floats = 144B): lanes in an 8-lane phase
//    hit banks 4t..4t+3 -> all 32 banks exactly once.
//  - coalesced i4-indexed float4: same property.
#define PAD4(i) ((i) + (((i) >> 5) << 2))

__device__ __forceinline__ float pow2k(float a, int sq) {
    #pragma unroll
    for (int i = 0; i < sq; i++) a *= a;
    return a;
}

__global__ void __launch_bounds__(THREADS) fused(const float* __restrict__ x,
                                                 const float* __restrict__ z_alpha,
                                                 const float* __restrict__ log_threshold,
                                                 const float* __restrict__ log_ratio,
                                                 const float* __restrict__ log_knee,
                                                 float* __restrict__ out) {
    __shared__ __align__(16) float s[CHUNK + CHUNK / 8];
    __shared__ float wsum[NW];
    __shared__ float wred[NW];
    __shared__ float s_carry;

    const int b = blockIdx.x;
    const int n = b / CPR;
    const int c = b % CPR;
    const int tid = threadIdx.x;
    const int lane = tid & 31;
    const int wid = tid >> 5;

    const float alpha = 1.f / (1.f + expf(-z_alpha[n]));
    const float one_m = 1.f - alpha;
    const float a32   = pow2k(alpha, 5);     // alpha^32   (per-segment decay)
    const float a1024 = pow2k(a32, 5);       // alpha^1024 (warp decay & window step)
    const float aK    = pow2k(a1024, 4);     // alpha^16384
    const float l2a   = log2f(alpha);

    const float* __restrict__ xr = x + (size_t)n * (NCH * LEN);
    const int base = c * CHUNK;

    // ---- Prologue A: u[t] = (1-a)*(loud[t] - a^K * loud[t-K]) into smem (f4)
    const float4* __restrict__ x4a = (const float4*)xr;
    const float4* __restrict__ x4b = (const float4*)(xr + LEN);
    const float haK = 0.5f * aK;
    for (int i4 = tid; i4 < CHUNK / 4; i4 += THREADS) {
        const int q = (base >> 2) + i4;
        const float4 xa = x4a[q];
        const float4 xb = x4b[q];
        float4 u;
        u.x = 0.5f * (xa.x * xa.x + xb.x * xb.x);
        u.y = 0.5f * (xa.y * xa.y + xb.y * xb.y);
        u.z = 0.5f * (xa.z * xa.z + xb.z * xb.z);
        u.w = 0.5f * (xa.w * xa.w + xb.w * xb.w);
        if (c >= 2) {  // lag t-K valid exactly when c >= 2
            const int ql = q - (KIIR >> 2);
            const float4 la = x4a[ql];
            const float4 lb = x4b[ql];
            u.x -= haK * (la.x * la.x + lb.x * lb.x);
            u.y -= haK * (la.y * la.y + lb.y * lb.y);
            u.z -= haK * (la.z * la.z + lb.z * lb.z);
            u.w -= haK * (la.w * la.w + lb.w * lb.w);
        }
        u.x *= one_m; u.y *= one_m; u.z *= one_m; u.w *= one_m;
        *(float4*)&s[PAD4(i4 * 4)] = u;
    }

    // ---- Prologue B: incoming state via vectorized windowed reduction.
    //   E_prev = env[base-1] = (1-a) * sum_{m=0}^{K-1} a^(K-1-m) loud[base-K+m]
    //   Thread t owns float4 groups m = 1024*j + 4t; Horner in j with a^1024,
    //   in-group weights a^3..a^0, final scale a^(1020-4t).
    float S = 0.f;
    if (c > 0) {
        const int w0 = base - KIIR;
        const float h0 = 0.5f;
        const float h1 = 0.5f * alpha;
        const float h2 = h1 * alpha;
        const float h3 = h2 * alpha;
        #pragma unroll
        for (int j = 0; j < WIN_J; j++) {
            const int p = w0 + j * (4 * THREADS) + tid * 4;
            float l = 0.f;
            if (p >= 0) {
                const float4 xa = x4a[p >> 2];
                const float4 xb = x4b[p >> 2];
                l = h3 * (xa.x * xa.x + xb.x * xb.x);
                l = fmaf(h2, xa.y * xa.y + xb.y * xb.y, l);
                l = fmaf(h1, xa.z * xa.z + xb.z * xb.z, l);
                l = fmaf(h0, xa.w * xa.w + xb.w * xb.w, l);
            }
            S = fmaf(S, a1024, l);
        }
        S *= exp2f((float)(4 * THREADS - 4 - 4 * tid) * l2a);  // a^(1020-4t)
    }
    #pragma unroll
    for (int d = 16; d > 0; d >>= 1) S += __shfl_down_sync(0xffffffffu, S, d);
    if (lane == 0) wred[wid] = S;
    __syncthreads();

    // ---- Pass 1: per-thread segment total via 8 LDS.128
    const int sbase = 36 * tid;   // == PAD4(tid*32)
    float acc = 0.f;
    #pragma unroll
    for (int k = 0; k < SEG / 4; k++) {
        const float4 u4 = *(const float4*)&s[sbase + 4 * k];
        acc = fmaf(alpha, acc, u4.x);
        acc = fmaf(alpha, acc, u4.y);
        acc = fmaf(alpha, acc, u4.z);
        acc = fmaf(alpha, acc, u4.w);
    }

    // ---- Warp scan of segment totals (decay a32)
    float v = acc;
    float pw = a32;
    #pragma unroll
    for (int d = 1; d < 32; d <<= 1) {
        const float up = __shfl_up_sync(0xffffffffu, v, d);
        if (lane >= d) v = fmaf(pw, up, v);
        pw *= pw;
    }
    if (lane == 31) wsum[wid] = v;
    __syncthreads();

    // ---- Warp 0: scan 8 warp totals (decay a1024). Warp 1: finish E_prev.
    if (wid == 0) {
        float w = (lane < NW) ? wsum[lane] : 0.f;
        float pw2 = a1024;
        #pragma unroll
        for (int d = 1; d < NW; d <<= 1) {
            const float up = __shfl_up_sync(0xffffffffu, w, d);
            if (lane >= d) w = fmaf(pw2, up, w);
            pw2 *= pw2;
        }
        if (lane < NW) wsum[lane] = w;
    }
    if (wid == 1) {
        float t = (lane < NW) ? wred[lane] : 0.f;
        #pragma unroll
        for (int d = NW / 2; d > 0; d >>= 1) t += __shfl_down_sync(0xffffffffu, t, d);
        if (lane == 0) s_carry = one_m * t;   // E_prev
    }
    __syncthreads();

    // ---- Pass 2: rescan smem in place (f4 in, f4 out) with carry folded in.
    const float G = s_carry;
    const float Wprev = (wid > 0) ? wsum[wid - 1] : 0.f;
    float vex = __shfl_up_sync(0xffffffffu, v, 1);
    if (lane == 0) vex = 0.f;
    float acc2 = vex + exp2f((float)(SEG * lane) * l2a) * Wprev
                     + G * exp2f((float)(SEG * tid) * l2a);
    #pragma unroll
    for (int k = 0; k < SEG / 4; k++) {
        float4 u4 = *(const float4*)&s[sbase + 4 * k];
        acc2 = fmaf(alpha, acc2, u4.x); u4.x = acc2;
        acc2 = fmaf(alpha, acc2, u4.y); u4.y = acc2;
        acc2 = fmaf(alpha, acc2, u4.z); u4.z = acc2;
        acc2 = fmaf(alpha, acc2, u4.w); u4.w = acc2;
        *(float4*)&s[sbase + 4 * k] = u4;   // s now holds GLOBAL env
    }
    __syncthreads();

    // ---- Epilogue: gain from env (f4 LDS), multiply, coalesced f4 store
    const float Tl2   = (log_threshold[n] - 6.f) * 1.44269504088896f; // T/ln2
    const float ratio = 1.f + expf(log_ratio[n]);
    const float knee  = expf(log_knee[n] - 1.f);
    const float coef  = (1.f / ratio - 1.f) / knee;

    float4* __restrict__ o4a = (float4*)(out + (size_t)n * (NCH * LEN));
    float4* __restrict__ o4b = (float4*)(out + (size_t)n * (NCH * LEN) + LEN);

    for (int i4 = tid; i4 < CHUNK / 4; i4 += THREADS) {
        const int q = (base >> 2) + i4;
        const float4 e4 = *(const float4*)&s[PAD4(i4 * 4)];

        const float ev[4] = {e4.x, e4.y, e4.z, e4.w};
        float g[4];
        #pragma unroll
        for (int k = 0; k < 4; k++) {
            const float w   = ev[k] + 1e-5f;
            const float t1  = __log2f(w);
            const float arg = knee * (t1 - Tl2);
            const float E   = exp2f(arg);
            float lg = __log2f(1.f + E);
            if (arg > 24.f) lg = arg;     // softplus asymptote / overflow guard
            g[k] = exp2f(coef * lg);
        }

        const float4 xa = x4a[q];         // L1/L2-hot (loaded in prologue)
        const float4 xb = x4b[q];
        float4 oa, ob;
        oa.x = g[0] * xa.x;  ob.x = g[0] * xb.x;
        oa.y = g[1] * xa.y;  ob.y = g[1] * xb.y;
        oa.z = g[2] * xa.z;  ob.z = g[2] * xb.z;
        oa.w = g[3] * xa.w;  ob.w = g[3] * xb.w;
        o4a[q] = oa;
        o4b[q] = ob;
    }
}

extern "C" void kernel_launch(void* const* d_in, const int* in_sizes, int n_in,
                              void* d_out, int out_size) {
    const float* x  = (const float*)d_in[0];
    const float* za = (const float*)d_in[1];
    const float* lt = (const float*)d_in[2];
    const float* lr = (const float*)d_in[3];
    const float* lk = (const float*)d_in[4];
    float* out = (float*)d_out;

    fused<<<NBLK, THREADS>>>(x, za, lt, lr, lk, out);
}

// round 12
// speedup vs baseline: 1.2150x; 1.2150x over previous
#include <cuda_runtime.h>
#include <math.h>

// Fixed problem shape
#define NROWS 32
#define NCH   2
#define LEN   131072
#define KIIR  16384            // FIR truncation; == 2*CHUNK
#define CHUNK 8192
#define THREADS 256
#define SEG   32               // CHUNK == THREADS*SEG
#define NW    (THREADS / 32)   // 8 warps
#define CPR   16               // chunks per row
#define NBLK  (NROWS * CPR)    // 512
#define WIN_J (KIIR / (4 * THREADS)) // 16 float4 Horner steps per thread

// Padded smem index (kills 32-way bank conflicts on per-thread segments)
#define PAD(i) ((i) + ((i) >> 5))

__device__ __forceinline__ float pow2k(float a, int sq) {
    #pragma unroll
    for (int i = 0; i < sq; i++) a *= a;
    return a;
}

__global__ void __launch_bounds__(THREADS) fused(const float* __restrict__ x,
                                                 const float* __restrict__ z_alpha,
                                                 const float* __restrict__ log_threshold,
                                                 const float* __restrict__ log_ratio,
                                                 const float* __restrict__ log_knee,
                                                 float* __restrict__ out) {
    __shared__ float s[CHUNK + CHUNK / 32];
    __shared__ float wsum[NW];
    __shared__ float wred[NW];
    __shared__ float s_carry;

    const int b = blockIdx.x;
    const int n = b / CPR;
    const int c = b % CPR;
    const int tid = threadIdx.x;
    const int lane = tid & 31;
    const int wid = tid >> 5;

    const float alpha = 1.f / (1.f + expf(-z_alpha[n]));
    const float one_m = 1.f - alpha;
    const float a32   = pow2k(alpha, 5);     // alpha^32   (per-segment decay)
    const float a1024 = pow2k(a32, 5);       // alpha^1024 (warp decay & window step)
    const float aK    = pow2k(a1024, 4);     // alpha^16384
    const float l2a   = log2f(alpha);

    // Adaptive truncation: contributions weighted below 2^-30 (~1e-9) of the
    // current sample are dropped. Deterministic, block-uniform.
    //   window: need alpha^m > 1e-9  ->  m < 30/(-l2a); round up to 1024-blocks
    const float mneed = 30.f / fmaxf(-l2a, 1e-6f);
    int jb = (int)(mneed * (1.f / 1024.f)) + 1;      // # of trailing j-blocks
    if (jb > WIN_J) jb = WIN_J;
    const int j_start = WIN_J - jb;
    //   lag term: weight aK; skip when negligible
    const bool use_lag = (c >= 2) && (aK > 1e-10f);

    const float* __restrict__ xr = x + (size_t)n * (NCH * LEN);
    const int base = c * CHUNK;

    // ---- Prologue A: u[t] = (1-a)*(loud[t] - a^K * loud[t-K]) into smem
    const float4* __restrict__ x4a = (const float4*)xr;
    const float4* __restrict__ x4b = (const float4*)(xr + LEN);
    const float haK = 0.5f * aK;
    for (int i4 = tid; i4 < CHUNK / 4; i4 += THREADS) {
        const int i = i4 * 4;
        const int q = (base >> 2) + i4;
        const float4 xa = x4a[q];
        const float4 xb = x4b[q];
        float4 u;
        u.x = 0.5f * (xa.x * xa.x + xb.x * xb.x);
        u.y = 0.5f * (xa.y * xa.y + xb.y * xb.y);
        u.z = 0.5f * (xa.z * xa.z + xb.z * xb.z);
        u.w = 0.5f * (xa.w * xa.w + xb.w * xb.w);
        if (use_lag) {
            const int ql = q - (KIIR >> 2);
            const float4 la = x4a[ql];
            const float4 lb = x4b[ql];
            u.x -= haK * (la.x * la.x + lb.x * lb.x);
            u.y -= haK * (la.y * la.y + lb.y * lb.y);
            u.z -= haK * (la.z * la.z + lb.z * lb.z);
            u.w -= haK * (la.w * la.w + lb.w * lb.w);
        }
        s[PAD(i)]     = one_m * u.x;
        s[PAD(i + 1)] = one_m * u.y;
        s[PAD(i + 2)] = one_m * u.z;
        s[PAD(i + 3)] = one_m * u.w;
    }

    // ---- Prologue B: incoming state via truncated, vectorized reduction.
    //   E_prev = env[base-1] = (1-a) * sum_{m=0}^{K-1} a^(K-1-m) loud[base-K+m]
    //   Thread t owns float4 groups m = 1024*j + 4t; Horner in j with a^1024,
    //   in-group weights a^3..a^0, final scale a^(1020-4t). Iterations with
    //   total weight < 1e-9 are skipped (j < j_start).
    float S = 0.f;
    if (c > 0) {
        const int w0 = base - KIIR;
        const float h0 = 0.5f;
        const float h1 = 0.5f * alpha;
        const float h2 = h1 * alpha;
        const float h3 = h2 * alpha;
        for (int j = j_start; j < WIN_J; j++) {
            const int p = w0 + j * (4 * THREADS) + tid * 4;
            float l = 0.f;
            if (p >= 0) {
                const float4 xa = x4a[p >> 2];
                const float4 xb = x4b[p >> 2];
                l = h3 * (xa.x * xa.x + xb.x * xb.x);
                l = fmaf(h2, xa.y * xa.y + xb.y * xb.y, l);
                l = fmaf(h1, xa.z * xa.z + xb.z * xb.z, l);
                l = fmaf(h0, xa.w * xa.w + xb.w * xb.w, l);
            }
            S = fmaf(S, a1024, l);
        }
        S *= exp2f((float)(4 * THREADS - 4 - 4 * tid) * l2a);  // a^(1020-4t)
    }
    #pragma unroll
    for (int d = 16; d > 0; d >>= 1) S += __shfl_down_sync(0xffffffffu, S, d);
    if (lane == 0) wred[wid] = S;
    __syncthreads();

    // ---- Pass 1: per-thread segment total (no per-element storage)
    const int sb = PAD(tid * SEG);
    float acc = 0.f;
    #pragma unroll
    for (int j = 0; j < SEG; j++)
        acc = fmaf(alpha, acc, s[sb + j]);

    // ---- Warp scan of segment totals (decay a32)
    float v = acc;
    float pw = a32;
    #pragma unroll
    for (int d = 1; d < 32; d <<= 1) {
        const float up = __shfl_up_sync(0xffffffffu, v, d);
        if (lane >= d) v = fmaf(pw, up, v);
        pw *= pw;
    }
    if (lane == 31) wsum[wid] = v;
    __syncthreads();

    // ---- Warp 0: scan 8 warp totals (decay a1024). Warp 1: finish E_prev.
    if (wid == 0) {
        float w = (lane < NW) ? wsum[lane] : 0.f;
        float pw2 = a1024;
        #pragma unroll
        for (int d = 1; d < NW; d <<= 1) {
            const float up = __shfl_up_sync(0xffffffffu, w, d);
            if (lane >= d) w = fmaf(pw2, up, w);
            pw2 *= pw2;
        }
        if (lane < NW) wsum[lane] = w;
    }
    if (wid == 1) {
        float t = (lane < NW) ? wred[lane] : 0.f;
        #pragma unroll
        for (int d = NW / 2; d > 0; d >>= 1) t += __shfl_down_sync(0xffffffffu, t, d);
        if (lane == 0) s_carry = one_m * t;   // E_prev
    }
    __syncthreads();

    // ---- Pass 2: rescan smem in place with full carry folded in.
    //      acc0 = warp-exclusive + a^(32*lane)*Wprev + E_prev*a^(32*tid)
    const float G = s_carry;
    const float Wprev = (wid > 0) ? wsum[wid - 1] : 0.f;
    float vex = __shfl_up_sync(0xffffffffu, v, 1);
    if (lane == 0) vex = 0.f;
    float acc2 = vex + exp2f((float)(SEG * lane) * l2a) * Wprev
                     + G * exp2f((float)(SEG * tid) * l2a);
    #pragma unroll
    for (int j = 0; j < SEG; j++) {
        acc2 = fmaf(alpha, acc2, s[sb + j]);
        s[sb + j] = acc2;                 // s now holds GLOBAL env
    }
    __syncthreads();

    // ---- Epilogue: gain from env, multiply, coalesced float4
    const float Tl2   = (log_threshold[n] - 6.f) * 1.44269504088896f; // T/ln2
    const float ratio = 1.f + expf(log_ratio[n]);
    const float knee  = expf(log_knee[n] - 1.f);
    const float coef  = (1.f / ratio - 1.f) / knee;

    float4* __restrict__ o4a = (float4*)(out + (size_t)n * (NCH * LEN));
    float4* __restrict__ o4b = (float4*)(out + (size_t)n * (NCH * LEN) + LEN);

    for (int i4 = tid; i4 < CHUNK / 4; i4 += THREADS) {
        const int i = i4 * 4;
        const int q = (base >> 2) + i4;

        const float ev[4] = {s[PAD(i)], s[PAD(i + 1)], s[PAD(i + 2)], s[PAD(i + 3)]};
        float g[4];
        #pragma unroll
        for (int k = 0; k < 4; k++) {
            const float w   = ev[k] + 1e-5f;
            const float t1  = __log2f(w);
            const float arg = knee * (t1 - Tl2);
            const float E   = exp2f(arg);
            float lg = __log2f(1.f + E);
            if (arg > 24.f) lg = arg;     // softplus asymptote / overflow guard
            g[k] = exp2f(coef * lg);
        }

        const float4 xa = x4a[q];         // L1/L2-hot (loaded in prologue)
        const float4 xb = x4b[q];
        float4 oa, ob;
        oa.x = g[0] * xa.x;  ob.x = g[0] * xb.x;
        oa.y = g[1] * xa.y;  ob.y = g[1] * xb.y;
        oa.z = g[2] * xa.z;  ob.z = g[2] * xb.z;
        oa.w = g[3] * xa.w;  ob.w = g[3] * xb.w;
        o4a[q] = oa;
        o4b[q] = ob;
    }
}

extern "C" void kernel_launch(void* const* d_in, const int* in_sizes, int n_in,
                              void* d_out, int out_size) {
    const float* x  = (const float*)d_in[0];
    const float* za = (const float*)d_in[1];
    const float* lt = (const float*)d_in[2];
    const float* lr = (const float*)d_in[3];
    const float* lk = (const float*)d_in[4];
    float* out = (float*)d_out;

    fused<<<NBLK, THREADS>>>(x, za, lt, lr, lk, out);
}

// round 13
// speedup vs baseline: 1.2334x; 1.0152x over previous
#include <cuda_runtime.h>
#include <math.h>

// Fixed problem shape
#define NROWS 32
#define NCH   2
#define LEN   131072
#define KIIR  16384            // FIR truncation; == 4*CHUNK
#define CHUNK 4096
#define THREADS 256
#define SEG   16               // CHUNK == THREADS*SEG
#define NW    (THREADS / 32)   // 8 warps
#define CPR   32               // chunks per row
#define NBLK  (NROWS * CPR)    // 1024
#define WIN_J (KIIR / (4 * THREADS)) // 16 float4 Horner steps per thread

// Padded smem index (kills 32-way bank conflicts on per-thread segments)
#define PAD(i) ((i) + ((i) >> 5))

__device__ __forceinline__ float pow2k(float a, int sq) {
    #pragma unroll
    for (int i = 0; i < sq; i++) a *= a;
    return a;
}

__global__ void __launch_bounds__(THREADS) fused(const float* __restrict__ x,
                                                 const float* __restrict__ z_alpha,
                                                 const float* __restrict__ log_threshold,
                                                 const float* __restrict__ log_ratio,
                                                 const float* __restrict__ log_knee,
                                                 float* __restrict__ out) {
    __shared__ float s[CHUNK + CHUNK / 32];
    __shared__ float wsum[NW];
    __shared__ float wred[NW];
    __shared__ float s_carry;

    const int b = blockIdx.x;
    const int n = b / CPR;
    const int c = b % CPR;
    const int tid = threadIdx.x;
    const int lane = tid & 31;
    const int wid = tid >> 5;

    const float alpha = 1.f / (1.f + expf(-z_alpha[n]));
    const float one_m = 1.f - alpha;
    const float a16   = pow2k(alpha, 4);     // alpha^16   (per-segment decay)
    const float a512  = pow2k(a16, 5);       // alpha^512  (per-warp decay)
    const float a1024 = a512 * a512;         // alpha^1024 (window Horner step)
    const float aK    = pow2k(a1024, 4);     // alpha^16384
    const float l2a   = log2f(alpha);

    // Adaptive truncation: contributions weighted below 2^-30 (~1e-9) of the
    // current sample are dropped. Deterministic, block-uniform.
    const float mneed = 30.f / fmaxf(-l2a, 1e-6f);
    int jb = (int)(mneed * (1.f / 1024.f)) + 1;      // # of trailing j-blocks
    if (jb > WIN_J) jb = WIN_J;
    const int j_start = WIN_J - jb;
    const bool use_lag = (c >= 4) && (aK > 1e-10f);  // KIIR == 4*CHUNK

    const float* __restrict__ xr = x + (size_t)n * (NCH * LEN);
    const int base = c * CHUNK;

    // ---- Prologue A: u[t] = (1-a)*(loud[t] - a^K * loud[t-K]) into smem
    const float4* __restrict__ x4a = (const float4*)xr;
    const float4* __restrict__ x4b = (const float4*)(xr + LEN);
    const float haK = 0.5f * aK;
    for (int i4 = tid; i4 < CHUNK / 4; i4 += THREADS) {
        const int i = i4 * 4;
        const int q = (base >> 2) + i4;
        const float4 xa = x4a[q];
        const float4 xb = x4b[q];
        float4 u;
        u.x = 0.5f * (xa.x * xa.x + xb.x * xb.x);
        u.y = 0.5f * (xa.y * xa.y + xb.y * xb.y);
        u.z = 0.5f * (xa.z * xa.z + xb.z * xb.z);
        u.w = 0.5f * (xa.w * xa.w + xb.w * xb.w);
        if (use_lag) {
            const int ql = q - (KIIR >> 2);
            const float4 la = x4a[ql];
            const float4 lb = x4b[ql];
            u.x -= haK * (la.x * la.x + lb.x * lb.x);
            u.y -= haK * (la.y * la.y + lb.y * lb.y);
            u.z -= haK * (la.z * la.z + lb.z * lb.z);
            u.w -= haK * (la.w * la.w + lb.w * lb.w);
        }
        s[PAD(i)]     = one_m * u.x;
        s[PAD(i + 1)] = one_m * u.y;
        s[PAD(i + 2)] = one_m * u.z;
        s[PAD(i + 3)] = one_m * u.w;
    }

    // ---- Prologue B: incoming state via truncated, vectorized reduction.
    //   E_prev = env[base-1] = (1-a) * sum_{m=0}^{K-1} a^(K-1-m) loud[base-K+m]
    //   Thread t owns float4 groups m = 1024*j + 4t; Horner in j with a^1024,
    //   in-group weights a^3..a^0, final scale a^(1020-4t). Iterations with
    //   total weight < 1e-9 are skipped (j < j_start).
    float S = 0.f;
    if (c > 0) {
        const int w0 = base - KIIR;
        const float h0 = 0.5f;
        const float h1 = 0.5f * alpha;
        const float h2 = h1 * alpha;
        const float h3 = h2 * alpha;
        for (int j = j_start; j < WIN_J; j++) {
            const int p = w0 + j * (4 * THREADS) + tid * 4;
            float l = 0.f;
            if (p >= 0) {
                const float4 xa = x4a[p >> 2];
                const float4 xb = x4b[p >> 2];
                l = h3 * (xa.x * xa.x + xb.x * xb.x);
                l = fmaf(h2, xa.y * xa.y + xb.y * xb.y, l);
                l = fmaf(h1, xa.z * xa.z + xb.z * xb.z, l);
                l = fmaf(h0, xa.w * xa.w + xb.w * xb.w, l);
            }
            S = fmaf(S, a1024, l);
        }
        S *= exp2f((float)(4 * THREADS - 4 - 4 * tid) * l2a);  // a^(1020-4t)
    }
    #pragma unroll
    for (int d = 16; d > 0; d >>= 1) S += __shfl_down_sync(0xffffffffu, S, d);
    if (lane == 0) wred[wid] = S;
    __syncthreads();

    // ---- Pass 1: per-thread segment total (no per-element storage)
    const int sb = PAD(tid * SEG);
    float acc = 0.f;
    #pragma unroll
    for (int j = 0; j < SEG; j++)
        acc = fmaf(alpha, acc, s[sb + j]);

    // ---- Warp scan of segment totals (decay a16)
    float v = acc;
    float pw = a16;
    #pragma unroll
    for (int d = 1; d < 32; d <<= 1) {
        const float up = __shfl_up_sync(0xffffffffu, v, d);
        if (lane >= d) v = fmaf(pw, up, v);
        pw *= pw;
    }
    if (lane == 31) wsum[wid] = v;
    __syncthreads();

    // ---- Warp 0: scan 8 warp totals (decay a512). Warp 1: finish E_prev.
    if (wid == 0) {
        float w = (lane < NW) ? wsum[lane] : 0.f;
        float pw2 = a512;
        #pragma unroll
        for (int d = 1; d < NW; d <<= 1) {
            const float up = __shfl_up_sync(0xffffffffu, w, d);
            if (lane >= d) w = fmaf(pw2, up, w);
            pw2 *= pw2;
        }
        if (lane < NW) wsum[lane] = w;
    }
    if (wid == 1) {
        float t = (lane < NW) ? wred[lane] : 0.f;
        #pragma unroll
        for (int d = NW / 2; d > 0; d >>= 1) t += __shfl_down_sync(0xffffffffu, t, d);
        if (lane == 0) s_carry = one_m * t;   // E_prev
    }
    __syncthreads();

    // ---- Pass 2: rescan smem in place with full carry folded in.
    //      acc0 = warp-exclusive + a^(16*lane)*Wprev + E_prev*a^(16*tid)
    const float G = s_carry;
    const float Wprev = (wid > 0) ? wsum[wid - 1] : 0.f;
    float vex = __shfl_up_sync(0xffffffffu, v, 1);
    if (lane == 0) vex = 0.f;
    float acc2 = vex + exp2f((float)(SEG * lane) * l2a) * Wprev
                     + G * exp2f((float)(SEG * tid) * l2a);
    #pragma unroll
    for (int j = 0; j < SEG; j++) {
        acc2 = fmaf(alpha, acc2, s[sb + j]);
        s[sb + j] = acc2;                 // s now holds GLOBAL env
    }
    __syncthreads();

    // ---- Epilogue: gain from env, multiply, coalesced float4
    const float Tl2   = (log_threshold[n] - 6.f) * 1.44269504088896f; // T/ln2
    const float ratio = 1.f + expf(log_ratio[n]);
    const float knee  = expf(log_knee[n] - 1.f);
    const float coef  = (1.f / ratio - 1.f) / knee;

    float4* __restrict__ o4a = (float4*)(out + (size_t)n * (NCH * LEN));
    float4* __restrict__ o4b = (float4*)(out + (size_t)n * (NCH * LEN) + LEN);

    for (int i4 = tid; i4 < CHUNK / 4; i4 += THREADS) {
        const int i = i4 * 4;
        const int q = (base >> 2) + i4;

        const float ev[4] = {s[PAD(i)], s[PAD(i + 1)], s[PAD(i + 2)], s[PAD(i + 3)]};
        float g[4];
        #pragma unroll
        for (int k = 0; k < 4; k++) {
            const float w   = ev[k] + 1e-5f;
            const float t1  = __log2f(w);
            const float arg = knee * (t1 - Tl2);
            const float E   = exp2f(arg);
            float lg = __log2f(1.f + E);
            if (arg > 24.f) lg = arg;     // softplus asymptote / overflow guard
            g[k] = exp2f(coef * lg);
        }

        const float4 xa = x4a[q];         // L1/L2-hot (loaded in prologue)
        const float4 xb = x4b[q];
        float4 oa, ob;
        oa.x = g[0] * xa.x;  ob.x = g[0] * xb.x;
        oa.y = g[1] * xa.y;  ob.y = g[1] * xb.y;
        oa.z = g[2] * xa.z;  ob.z = g[2] * xb.z;
        oa.w = g[3] * xa.w;  ob.w = g[3] * xb.w;
        o4a[q] = oa;
        o4b[q] = ob;
    }
}

extern "C" void kernel_launch(void* const* d_in, const int* in_sizes, int n_in,
                              void* d_out, int out_size) {
    const float* x  = (const float*)d_in[0];
    const float* za = (const float*)d_in[1];
    const float* lt = (const float*)d_in[2];
    const float* lr = (const float*)d_in[3];
    const float* lk = (const float*)d_in[4];
    float* out = (float*)d_out;

    fused<<<NBLK, THREADS>>>(x, za, lt, lr, lk, out);
}

// round 14
// speedup vs baseline: 1.2695x; 1.0293x over previous
#include <cuda_runtime.h>
#include <math.h>

// Fixed problem shape
#define NROWS 32
#define NCH   2
#define LEN   131072
#define KIIR  16384            // FIR truncation; == 4*CHUNK
#define CHUNK 4096
#define THREADS 256
#define SEG   16               // CHUNK == THREADS*SEG
#define NW    (THREADS / 32)   // 8 warps
#define CPR   32               // chunks per row
#define NBLK  (NROWS * CPR)    // 1024  (== one full wave at 7 CTA/SM)
#define WIN_J (KIIR / (4 * THREADS)) // 16 float4 Horner steps per thread

// Padded smem index (kills 32-way bank conflicts on per-thread segments)
#define PAD(i) ((i) + ((i) >> 5))

__device__ __forceinline__ float pow2k(float a, int sq) {
    #pragma unroll
    for (int i = 0; i < sq; i++) a *= a;
    return a;
}

__global__ void __launch_bounds__(THREADS, 7) fused(const float* __restrict__ x,
                                                    const float* __restrict__ z_alpha,
                                                    const float* __restrict__ log_threshold,
                                                    const float* __restrict__ log_ratio,
                                                    const float* __restrict__ log_knee,
                                                    float* __restrict__ out) {
    __shared__ float s[CHUNK + CHUNK / 32];
    __shared__ float wsum[NW];
    __shared__ float wred[NW];
    __shared__ float s_carry;

    const int b = blockIdx.x;
    const int n = b / CPR;
    const int c = b % CPR;
    const int tid = threadIdx.x;
    const int lane = tid & 31;
    const int wid = tid >> 5;

    const float alpha = 1.f / (1.f + expf(-z_alpha[n]));
    const float one_m = 1.f - alpha;
    const float a16   = pow2k(alpha, 4);     // alpha^16   (per-segment decay)
    const float a512  = pow2k(a16, 5);       // alpha^512  (per-warp decay)
    const float a1024 = a512 * a512;         // alpha^1024 (window Horner step)
    const float aK    = pow2k(a1024, 4);     // alpha^16384
    const float l2a   = log2f(alpha);

    // Adaptive truncation: contributions weighted below 2^-30 (~1e-9) of the
    // current sample are dropped. Deterministic, block-uniform.
    const float mneed = 30.f / fmaxf(-l2a, 1e-6f);
    int jb = (int)(mneed * (1.f / 1024.f)) + 1;      // # of trailing j-blocks
    if (jb > WIN_J) jb = WIN_J;
    const int j_start = WIN_J - jb;
    const bool use_lag = (c >= 4) && (aK > 1e-10f);  // KIIR == 4*CHUNK

    const float* __restrict__ xr = x + (size_t)n * (NCH * LEN);
    const int base = c * CHUNK;

    // ---- Prologue A: u[t] = (1-a)*(loud[t] - a^K * loud[t-K]) into smem
    const float4* __restrict__ x4a = (const float4*)xr;
    const float4* __restrict__ x4b = (const float4*)(xr + LEN);
    const float haK = 0.5f * aK;
    for (int i4 = tid; i4 < CHUNK / 4; i4 += THREADS) {
        const int i = i4 * 4;
        const int q = (base >> 2) + i4;
        const float4 xa = x4a[q];
        const float4 xb = x4b[q];
        float4 u;
        u.x = 0.5f * (xa.x * xa.x + xb.x * xb.x);
        u.y = 0.5f * (xa.y * xa.y + xb.y * xb.y);
        u.z = 0.5f * (xa.z * xa.z + xb.z * xb.z);
        u.w = 0.5f * (xa.w * xa.w + xb.w * xb.w);
        if (use_lag) {
            const int ql = q - (KIIR >> 2);
            const float4 la = x4a[ql];
            const float4 lb = x4b[ql];
            u.x -= haK * (la.x * la.x + lb.x * lb.x);
            u.y -= haK * (la.y * la.y + lb.y * lb.y);
            u.z -= haK * (la.z * la.z + lb.z * lb.z);
            u.w -= haK * (la.w * la.w + lb.w * lb.w);
        }
        s[PAD(i)]     = one_m * u.x;
        s[PAD(i + 1)] = one_m * u.y;
        s[PAD(i + 2)] = one_m * u.z;
        s[PAD(i + 3)] = one_m * u.w;
    }

    // ---- Prologue B: incoming state via truncated, vectorized reduction.
    //   E_prev = env[base-1] = (1-a) * sum_{m=0}^{K-1} a^(K-1-m) loud[base-K+m]
    //   Thread t owns float4 groups m = 1024*j + 4t; Horner in j with a^1024,
    //   in-group weights a^3..a^0, final scale a^(1020-4t). Iterations with
    //   total weight < 1e-9 are skipped (j < j_start).
    float S = 0.f;
    if (c > 0) {
        const int w0 = base - KIIR;
        const float h0 = 0.5f;
        const float h1 = 0.5f * alpha;
        const float h2 = h1 * alpha;
        const float h3 = h2 * alpha;
        for (int j = j_start; j < WIN_J; j++) {
            const int p = w0 + j * (4 * THREADS) + tid * 4;
            float l = 0.f;
            if (p >= 0) {
                const float4 xa = x4a[p >> 2];
                const float4 xb = x4b[p >> 2];
                l = h3 * (xa.x * xa.x + xb.x * xb.x);
                l = fmaf(h2, xa.y * xa.y + xb.y * xb.y, l);
                l = fmaf(h1, xa.z * xa.z + xb.z * xb.z, l);
                l = fmaf(h0, xa.w * xa.w + xb.w * xb.w, l);
            }
            S = fmaf(S, a1024, l);
        }
        S *= exp2f((float)(4 * THREADS - 4 - 4 * tid) * l2a);  // a^(1020-4t)
    }
    #pragma unroll
    for (int d = 16; d > 0; d >>= 1) S += __shfl_down_sync(0xffffffffu, S, d);
    if (lane == 0) wred[wid] = S;
    __syncthreads();

    // ---- Pass 1: per-thread segment total (no per-element storage)
    const int sb = PAD(tid * SEG);
    float acc = 0.f;
    #pragma unroll
    for (int j = 0; j < SEG; j++)
        acc = fmaf(alpha, acc, s[sb + j]);

    // ---- Warp scan of segment totals (decay a16)
    float v = acc;
    float pw = a16;
    #pragma unroll
    for (int d = 1; d < 32; d <<= 1) {
        const float up = __shfl_up_sync(0xffffffffu, v, d);
        if (lane >= d) v = fmaf(pw, up, v);
        pw *= pw;
    }
    if (lane == 31) wsum[wid] = v;
    __syncthreads();

    // ---- Warp 0: scan 8 warp totals (decay a512). Warp 1: finish E_prev.
    if (wid == 0) {
        float w = (lane < NW) ? wsum[lane] : 0.f;
        float pw2 = a512;
        #pragma unroll
        for (int d = 1; d < NW; d <<= 1) {
            const float up = __shfl_up_sync(0xffffffffu, w, d);
            if (lane >= d) w = fmaf(pw2, up, w);
            pw2 *= pw2;
        }
        if (lane < NW) wsum[lane] = w;
    }
    if (wid == 1) {
        float t = (lane < NW) ? wred[lane] : 0.f;
        #pragma unroll
        for (int d = NW / 2; d > 0; d >>= 1) t += __shfl_down_sync(0xffffffffu, t, d);
        if (lane == 0) s_carry = one_m * t;   // E_prev
    }
    __syncthreads();

    // ---- Pass 2: rescan smem in place with full carry folded in.
    //      acc0 = warp-exclusive + a^(16*lane)*Wprev + E_prev*a^(16*tid)
    const float G = s_carry;
    const float Wprev = (wid > 0) ? wsum[wid - 1] : 0.f;
    float vex = __shfl_up_sync(0xffffffffu, v, 1);
    if (lane == 0) vex = 0.f;
    float acc2 = vex + exp2f((float)(SEG * lane) * l2a) * Wprev
                     + G * exp2f((float)(SEG * tid) * l2a);
    #pragma unroll
    for (int j = 0; j < SEG; j++) {
        acc2 = fmaf(alpha, acc2, s[sb + j]);
        s[sb + j] = acc2;                 // s now holds GLOBAL env
    }
    __syncthreads();

    // ---- Epilogue: gain from env, multiply, coalesced float4
    const float Tl2   = (log_threshold[n] - 6.f) * 1.44269504088896f; // T/ln2
    const float ratio = 1.f + expf(log_ratio[n]);
    const float knee  = expf(log_knee[n] - 1.f);
    const float coef  = (1.f / ratio - 1.f) / knee;

    float4* __restrict__ o4a = (float4*)(out + (size_t)n * (NCH * LEN));
    float4* __restrict__ o4b = (float4*)(out + (size_t)n * (NCH * LEN) + LEN);

    for (int i4 = tid; i4 < CHUNK / 4; i4 += THREADS) {
        const int i = i4 * 4;
        const int q = (base >> 2) + i4;

        const float ev[4] = {s[PAD(i)], s[PAD(i + 1)], s[PAD(i + 2)], s[PAD(i + 3)]};
        float g[4];
        #pragma unroll
        for (int k = 0; k < 4; k++) {
            const float w   = ev[k] + 1e-5f;
            const float t1  = __log2f(w);
            const float arg = knee * (t1 - Tl2);
            const float E   = exp2f(arg);
            float lg = __log2f(1.f + E);
            if (arg > 24.f) lg = arg;     // softplus asymptote / overflow guard
            g[k] = exp2f(coef * lg);
        }

        const float4 xa = x4a[q];         // L1/L2-hot (loaded in prologue)
        const float4 xb = x4b[q];
        float4 oa, ob;
        oa.x = g[0] * xa.x;  ob.x = g[0] * xb.x;
        oa.y = g[1] * xa.y;  ob.y = g[1] * xb.y;
        oa.z = g[2] * xa.z;  ob.z = g[2] * xb.z;
        oa.w = g[3] * xa.w;  ob.w = g[3] * xb.w;
        o4a[q] = oa;
        o4b[q] = ob;
    }
}

extern "C" void kernel_launch(void* const* d_in, const int* in_sizes, int n_in,
                              void* d_out, int out_size) {
    const float* x  = (const float*)d_in[0];
    const float* za = (const float*)d_in[1];
    const float* lt = (const float*)d_in[2];
    const float* lr = (const float*)d_in[3];
    const float* lk = (const float*)d_in[4];
    float* out = (float*)d_out;

    fused<<<NBLK, THREADS>>>(x, za, lt, lr, lk, out);
}